// round 2
// baseline (speedup 1.0000x reference)
#include <cuda_runtime.h>

#define CCH 256        // channels (all levels)
#define NIMG 2         // batch
#define OUTS 7
#define NBINS 49       // 7*7
#define HALF_BINS 25   // staging phase size
#define SPITCH 260     // staging pitch in floats (CCH+4): 16B-aligned, reduces dump conflicts
#define SPITCH4 65     // pitch in float4

// NHWC scratch for all 4 levels:
// L0: 2*256*256*256 = 33,554,432  @ 0
// L1: 2*128*128*256 =  8,388,608  @ 33,554,432
// L2: 2* 64* 64*256 =  2,097,152  @ 41,943,040
// L3: 2* 32* 32*256 =    524,288  @ 44,040,192
// total 44,564,480 floats (178.3 MB)
__device__ float g_nhwc[44564480];

__constant__ long long c_lvl_off[4] = {0LL, 33554432LL, 41943040LL, 44040192LL};

// ---------------------------------------------------------------------------
// NCHW [N,C,H,W] -> NHWC [N,H,W,C] tiled transpose (per n: [C,HW] -> [HW,C])
// grid: (HW/32, C/32, N), block (32,8)
// ---------------------------------------------------------------------------
__global__ __launch_bounds__(256) void transpose_kernel(
    const float* __restrict__ in, long long out_off, int HW)
{
    __shared__ float tile[32][33];
    const int hw0 = blockIdx.x * 32;
    const int c0  = blockIdx.y * 32;
    const int n   = blockIdx.z;
    const int tx = threadIdx.x, ty = threadIdx.y;

    const float* src = in + (size_t)n * CCH * HW;
    float* dst = g_nhwc + out_off + (size_t)n * HW * CCH;

#pragma unroll
    for (int j = 0; j < 32; j += 8)
        tile[ty + j][tx] = src[(size_t)(c0 + ty + j) * HW + (hw0 + tx)];
    __syncthreads();
#pragma unroll
    for (int j = 0; j < 32; j += 8)
        dst[(size_t)(hw0 + ty + j) * CCH + (c0 + tx)] = tile[tx][ty + j];
}

// ---------------------------------------------------------------------------
// ROIAlign pooler. One CTA per box. 256 threads:
//   q  = tid & 63  -> channel quad (float4 over 4 channels), coalesced across warp
//   bs = tid >> 6  -> bin set (4 sets strided over the phase's bins)
// Sample coords (14 per axis) + validity-masked bilinear weights in smem.
// Output staged in smem [bin][channel] in two 25/24-bin phases, then dumped
// TRANSPOSED to gmem as out[m][c][bin] (reference layout [M,C,7,7]) with
// consecutive threads writing consecutive bins (coalesced STG).
// ---------------------------------------------------------------------------
__global__ __launch_bounds__(256) void roi_pool_kernel(
    const float* __restrict__ boxes, float* __restrict__ out, int R)
{
    __shared__ float s_out[HALF_BINS * SPITCH];    // 26,000 B
    __shared__ int   s_i0[2][14], s_i1[2][14];
    __shared__ float s_h[2][14],  s_l[2][14];

    const int m   = blockIdx.x;
    const int tid = threadIdx.x;

    const float bx1 = __ldg(boxes + 4 * m + 0);
    const float by1 = __ldg(boxes + 4 * m + 1);
    const float bx2 = __ldg(boxes + 4 * m + 2);
    const float by2 = __ldg(boxes + 4 * m + 3);

    // assign_boxes_to_levels
    const float area = fmaxf((bx2 - bx1) * (by2 - by1), 0.0f);
    const float sz   = sqrtf(area);
    int lvl = (int)floorf(4.0f + log2f(sz / 224.0f + 1e-8f));
    lvl = min(max(lvl, 2), 5) - 2;                 // 0..3

    const int   Hd    = 256 >> lvl;                // square feature maps
    const int   Wd    = Hd;
    const float scale = 0.25f / (float)(1 << lvl);
    const int   n     = m / R;

    const float* fbase = g_nhwc + c_lvl_off[lvl] + (size_t)n * Hd * Wd * CCH;

    // 28 threads compute the 14 x-samples and 14 y-samples
    if (tid < 28) {
        const int axis = tid / 14;                 // 0 = x, 1 = y
        const int k    = tid - axis * 14;
        const float c1 = axis ? by1 : bx1;
        const float c2 = axis ? by2 : bx2;
        const int  lim = axis ? Hd : Wd;
        const float start = c1 * scale - 0.5f;
        const float end   = c2 * scale - 0.5f;
        const float bsz   = (end - start) / 7.0f;
        const float off   = (float)(k >> 1) + ((k & 1) ? 0.75f : 0.25f);
        const float t     = start + off * bsz;
        const bool  v     = (t >= -1.0f) && (t <= (float)lim);
        const float tc    = fminf(fmaxf(t, 0.0f), (float)(lim - 1));
        const int   i0    = (int)tc;               // tc >= 0 -> trunc == floor
        const int   i1    = min(i0 + 1, lim - 1);
        const float l     = tc - (float)i0;
        s_i0[axis][k] = i0;
        s_i1[axis][k] = i1;
        s_l[axis][k]  = v ? l : 0.0f;              // invalid sample -> zero weight
        s_h[axis][k]  = v ? (1.0f - l) : 0.0f;
    }
    __syncthreads();

    const int q  = tid & 63;
    const int bs = tid >> 6;
    const float4* base4 = reinterpret_cast<const float4*>(fbase) + q;
    float4* s4   = reinterpret_cast<float4*>(s_out);
    float* outm  = out + (size_t)m * (NBINS * CCH);   // [C][49]

#pragma unroll
    for (int phase = 0; phase < 2; ++phase) {
        const int b0   = phase * HALF_BINS;
        const int bcnt = phase ? (NBINS - HALF_BINS) : HALF_BINS;

        for (int bb = bs; bb < bcnt; bb += 4) {
            const int bin = b0 + bb;
            const int py  = bin / 7;
            const int px  = bin - py * 7;
            float4 acc = make_float4(0.f, 0.f, 0.f, 0.f);
#pragma unroll
            for (int sy = 0; sy < 2; ++sy) {
                const int   iy = py * 2 + sy;
                const int   r0 = s_i0[1][iy] * Wd;
                const int   r1 = s_i1[1][iy] * Wd;
                const float hy = s_h[1][iy];
                const float ly = s_l[1][iy];
#pragma unroll
                for (int sx = 0; sx < 2; ++sx) {
                    const int   ix = px * 2 + sx;
                    const int   x0 = s_i0[0][ix];
                    const int   x1 = s_i1[0][ix];
                    const float hx = s_h[0][ix];
                    const float lx = s_l[0][ix];
                    const float w00 = hy * hx, w01 = hy * lx;
                    const float w10 = ly * hx, w11 = ly * lx;
                    const float4 v00 = __ldg(base4 + (size_t)(r0 + x0) * 64);
                    const float4 v01 = __ldg(base4 + (size_t)(r0 + x1) * 64);
                    const float4 v10 = __ldg(base4 + (size_t)(r1 + x0) * 64);
                    const float4 v11 = __ldg(base4 + (size_t)(r1 + x1) * 64);
                    acc.x += w00 * v00.x + w01 * v01.x + w10 * v10.x + w11 * v11.x;
                    acc.y += w00 * v00.y + w01 * v01.y + w10 * v10.y + w11 * v11.y;
                    acc.z += w00 * v00.z + w01 * v01.z + w10 * v10.z + w11 * v11.z;
                    acc.w += w00 * v00.w + w01 * v01.w + w10 * v10.w + w11 * v11.w;
                }
            }
            acc.x *= 0.25f; acc.y *= 0.25f; acc.z *= 0.25f; acc.w *= 0.25f;
            s4[bb * SPITCH4 + q] = acc;            // [bin][channel], padded pitch
        }
        __syncthreads();

        // Transposed dump: i = c*bcnt + bb -> out[c*49 + b0 + bb].
        // Consecutive threads -> consecutive bins -> coalesced STG.
        const int cnt = bcnt * CCH;
        for (int i = tid; i < cnt; i += 256) {
            const int c  = i / bcnt;
            const int bb = i - c * bcnt;
            outm[c * NBINS + b0 + bb] = s_out[bb * SPITCH + c];
        }
        __syncthreads();
    }
}

// ---------------------------------------------------------------------------
extern "C" void kernel_launch(void* const* d_in, const int* in_sizes, int n_in,
                              void* d_out, int out_size)
{
    const float* f0    = (const float*)d_in[0];
    const float* f1    = (const float*)d_in[1];
    const float* f2    = (const float*)d_in[2];
    const float* f3    = (const float*)d_in[3];
    const float* boxes = (const float*)d_in[4];
    float*       out   = (float*)d_out;

    const int M = in_sizes[4] / 4;   // 1024 boxes
    const int R = M / NIMG;          // 512 per image

    const dim3 tb(32, 8);
    transpose_kernel<<<dim3(65536 / 32, CCH / 32, NIMG), tb>>>(f0, 0LL,        65536);
    transpose_kernel<<<dim3(16384 / 32, CCH / 32, NIMG), tb>>>(f1, 33554432LL, 16384);
    transpose_kernel<<<dim3( 4096 / 32, CCH / 32, NIMG), tb>>>(f2, 41943040LL,  4096);
    transpose_kernel<<<dim3( 1024 / 32, CCH / 32, NIMG), tb>>>(f3, 44040192LL,  1024);

    roi_pool_kernel<<<M, 256>>>(boxes, out, R);
}